// round 11
// baseline (speedup 1.0000x reference)
#include <cuda_runtime.h>
#include <math.h>

#define BB     8
#define NFULL  8192
#define NPART  2048
#define DLAT   512
#define EPSV   1e-12f

__device__ float g_pf[BB * NFULL];
__device__ float g_fp[BB * NFULL];
__device__ float g_part[BB * NPART];

constexpr int RBLKS = 120;
__device__ float g_partial[4 * RBLKS];

constexpr int THREADS = 128;              // 4 warps
constexpr int WARPS   = 4;
constexpr int Q       = 8;                // queries per thread (4 packed pairs)
constexpr int QP      = Q / 2;
constexpr int QPB     = THREADS * Q;      // 1024 queries per task
constexpr int CHUNK   = 512;              // refs per task

typedef unsigned long long u64;

__device__ __forceinline__ u64 pack2(float lo, float hi) {
    u64 r; asm("mov.b64 %0, {%1, %2};" : "=l"(r) : "f"(lo), "f"(hi)); return r;
}
__device__ __forceinline__ void unpack2(u64 v, float& lo, float& hi) {
    asm("mov.b64 {%0, %1}, %2;" : "=f"(lo), "=f"(hi) : "l"(v));
}
__device__ __forceinline__ u64 ffma2(u64 a, u64 b, u64 c) {
    u64 d; asm("fma.rn.f32x2 %0, %1, %2, %3;" : "=l"(d) : "l"(a), "l"(b), "l"(c)); return d;
}
// Warp-min of a NON-NEGATIVE float via integer redux (bit order == float order).
__device__ __forceinline__ float warp_min_pos(float v) {
    unsigned int r;
    asm("redux.sync.min.u32 %0, %1, 0xffffffff;"
        : "=r"(r) : "r"(__float_as_uint(v)));
    return __uint_as_float(r);
}

// ---------------------------------------------------------------------------
// Symmetric chamfer: tile (1024 pred-queries x 512 full-refs) computed once;
// row mins -> pf, col mins -> fp.  Fidelity tasks: rows only -> pp.
// t_ij = w_j - dot_ij ;  s_ij = u_i + t_ij = |q-r|^2/2 >= 0.
// ---------------------------------------------------------------------------
constexpr int RCK       = NFULL / CHUNK;             // 16
constexpr int CHAM_QT   = NFULL / QPB;               // 8
constexpr int FID_QT    = NPART / QPB;               // 2
constexpr int SYM_TASKS = CHAM_QT * RCK * BB;        // 1024
constexpr int FID_TASKS = FID_QT * RCK * BB;         // 256
constexpr int GRID      = SYM_TASKS + FID_TASKS;     // 1280

__global__ __launch_bounds__(THREADS)
void fused_rowmin_kernel(const float* __restrict__ pred,
                         const float* __restrict__ full,
                         const float* __restrict__ partial,
                         float* __restrict__ pf,
                         float* __restrict__ fp,
                         float* __restrict__ pp) {
    __shared__ ulonglong2 tA[CHUNK];            // (pack(x,x), pack(y,y))  8KB
    __shared__ ulonglong2 tB[CHUNK];            // (pack(z,z), pack(w,w))  8KB
    __shared__ float      colmin[WARPS][CHUNK]; // 8KB

    const int tid = threadIdx.x;
    const int wid = tid >> 5;
    const int lid = tid & 31;

    // ---- decode task ----
    const float *q, *r;
    float *rowout;
    bool sym;
    int b, ck, qt, Nq;
    int l = blockIdx.x;
    if (l < SYM_TASKS) {
        sym = true;
        b  = l >> 7;
        int rm = l & 127;
        ck = rm >> 3;
        qt = rm & 7;
        q = pred; r = full; rowout = pf; Nq = NFULL;
    } else {
        sym = false;
        l -= SYM_TASKS;
        b  = l >> 5;
        int rm = l & 31;
        ck = rm >> 1;
        qt = rm & 1;
        q = partial; r = pred; rowout = pp; Nq = NPART;
    }
    const int qbase = qt * QPB;
    const int rbase = ck * CHUNK;

    const float* qb = q + (size_t)b * Nq * 3;
    const float* rb = r + (size_t)b * NFULL * 3;

    // ---- tile load: dup-packed refs ----
    for (int j = tid; j < CHUNK; j += THREADS) {
        int rj = rbase + j;
        float x = rb[rj * 3 + 0];
        float y = rb[rj * 3 + 1];
        float z = rb[rj * 3 + 2];
        float w = 0.5f * (x * x + y * y + z * z);
        ulonglong2 a, bb;
        a.x  = pack2(x, x); a.y  = pack2(y, y);
        bb.x = pack2(z, z); bb.y = pack2(w, w);
        tA[j] = a;
        tB[j] = bb;
    }
    __syncthreads();

    // ---- per-thread queries: 4 packed pairs, negated coords; u kept scalar ----
    u64 nqx[QP], nqy[QP], nqz[QP];
    float u0r[QP], u1r[QP], m0[QP], m1[QP];
    const float* qrow = qb + (size_t)(qbase + tid * Q) * 3;
#pragma unroll
    for (int k = 0; k < QP; k++) {
        float x0 = qrow[6 * k + 0], y0 = qrow[6 * k + 1], z0 = qrow[6 * k + 2];
        float x1 = qrow[6 * k + 3], y1 = qrow[6 * k + 4], z1 = qrow[6 * k + 5];
        nqx[k] = pack2(-x0, -x1);
        nqy[k] = pack2(-y0, -y1);
        nqz[k] = pack2(-z0, -z1);
        u0r[k] = 0.5f * (x0 * x0 + y0 * y0 + z0 * z0);
        u1r[k] = 0.5f * (x1 * x1 + y1 * y1 + z1 * z1);
        m0[k]  = __int_as_float(0x7f800000);
        m1[k]  = __int_as_float(0x7f800000);
    }

    // ---- main loop: t = ww - dot via 3 chained FFMA2 ----
    if (sym) {
#pragma unroll 2
        for (int j = 0; j < CHUNK; j++) {
            ulonglong2 A = tA[j];
            ulonglong2 B = tB[j];
            float t0[QP], t1[QP];
#pragma unroll
            for (int k = 0; k < QP; k++) {
                u64 v = ffma2(nqz[k], B.x, B.y);
                v = ffma2(nqy[k], A.y, v);
                v = ffma2(nqx[k], A.x, v);
                unpack2(v, t0[k], t1[k]);
                m0[k] = fminf(m0[k], t0[k]);
                m1[k] = fminf(m1[k], t1[k]);
            }
            // col candidate: min_k (u_k + t_k), scalar adds on unpacked halves
            float ca = fminf(fminf(u0r[0] + t0[0], u0r[1] + t0[1]),
                             fminf(u0r[2] + t0[2], u0r[3] + t0[3]));
            float cb = fminf(fminf(u1r[0] + t1[0], u1r[1] + t1[1]),
                             fminf(u1r[2] + t1[2], u1r[3] + t1[3]));
            float cw = warp_min_pos(fminf(ca, cb));
            if (lid == 0) colmin[wid][j] = cw;
        }
    } else {
#pragma unroll 2
        for (int j = 0; j < CHUNK; j++) {
            ulonglong2 A = tA[j];
            ulonglong2 B = tB[j];
#pragma unroll
            for (int k = 0; k < QP; k++) {
                u64 v = ffma2(nqz[k], B.x, B.y);
                v = ffma2(nqy[k], A.y, v);
                v = ffma2(nqx[k], A.x, v);
                float s0, s1;
                unpack2(v, s0, s1);
                m0[k] = fminf(m0[k], s0);
                m1[k] = fminf(m1[k], s1);
            }
        }
    }

    // ---- row writeback: sq = 2 * (u + min t) ----
#pragma unroll
    for (int k = 0; k < QP; k++) {
        int qi = qbase + tid * Q + 2 * k;
        float s0 = fmaxf(2.0f * (u0r[k] + m0[k]), EPSV);
        float s1 = fmaxf(2.0f * (u1r[k] + m1[k]), EPSV);
        atomicMin((unsigned int*)&rowout[(size_t)b * Nq + qi],     __float_as_uint(s0));
        atomicMin((unsigned int*)&rowout[(size_t)b * Nq + qi + 1], __float_as_uint(s1));
    }

    // ---- col writeback (chamfer only): merge 4 warps ----
    if (sym) {
        __syncthreads();
        for (int j = tid; j < CHUNK; j += THREADS) {
            float v = fminf(fminf(colmin[0][j], colmin[1][j]),
                            fminf(colmin[2][j], colmin[3][j]));
            float sq = fmaxf(v + v, EPSV);
            atomicMin((unsigned int*)&fp[(size_t)b * NFULL + rbase + j],
                      __float_as_uint(sq));
        }
    }
}

// ---------------------------------------------------------------------------
__global__ __launch_bounds__(256)
void reduce1_kernel(const float* __restrict__ pf,
                    const float* __restrict__ fp,
                    const float* __restrict__ pp,
                    const float* __restrict__ mu,
                    const float* __restrict__ lv,
                    float* __restrict__ partials) {
    const int tid    = threadIdx.x;
    const int stride = gridDim.x * blockDim.x;
    const int g      = blockIdx.x * blockDim.x + tid;

    float s_pf = 0.f, s_fp = 0.f, s_pp = 0.f, s_kl = 0.f;
    for (int i = g; i < BB * NFULL; i += stride) {
        s_pf += sqrtf(pf[i]);
        s_fp += sqrtf(fp[i]);
    }
    for (int i = g; i < BB * NPART; i += stride) s_pp += sqrtf(pp[i]);
    for (int i = g; i < BB * DLAT; i += stride) {
        float m = mu[i], l = lv[i];
        s_kl += 1.0f + l - m * m - expf(l);
    }

    __shared__ float sh[4][8];
#pragma unroll
    for (int off = 16; off > 0; off >>= 1) {
        s_pf += __shfl_down_sync(0xffffffffu, s_pf, off);
        s_fp += __shfl_down_sync(0xffffffffu, s_fp, off);
        s_pp += __shfl_down_sync(0xffffffffu, s_pp, off);
        s_kl += __shfl_down_sync(0xffffffffu, s_kl, off);
    }
    int wid = tid >> 5, lid = tid & 31;
    if (lid == 0) { sh[0][wid] = s_pf; sh[1][wid] = s_fp; sh[2][wid] = s_pp; sh[3][wid] = s_kl; }
    __syncthreads();

    if (tid < 4) {
        float acc = 0.f;
#pragma unroll
        for (int w = 0; w < 8; w++) acc += sh[tid][w];
        partials[tid * RBLKS + blockIdx.x] = acc;
    }
}

// ---------------------------------------------------------------------------
__global__ __launch_bounds__(128)
void reduce2_kernel(const float* __restrict__ partials,
                    float* __restrict__ out) {
    const int tid = threadIdx.x;
    const int wid = tid >> 5;
    const int lid = tid & 31;

    float s = 0.f;
    for (int i = lid; i < RBLKS; i += 32) s += partials[wid * RBLKS + i];
#pragma unroll
    for (int off = 16; off > 0; off >>= 1)
        s += __shfl_down_sync(0xffffffffu, s, off);

    __shared__ float sums[4];
    if (lid == 0) sums[wid] = s;
    __syncthreads();

    if (tid == 0) {
        float inv_nf = 1.0f / (float)(BB * NFULL);
        float cd  = 0.5f * (sums[0] + sums[1]) * inv_nf;
        float fid = sums[2] / (float)(BB * NPART);
        float kl  = -0.5f * sums[3] / (float)BB;
        float total = 1.0f * cd + 0.01f * kl + 0.5f * fid;
        out[0] = total;
        out[1] = cd;
        out[2] = kl;
        out[3] = fid;
    }
}

// ---------------------------------------------------------------------------
extern "C" void kernel_launch(void* const* d_in, const int* in_sizes, int n_in,
                              void* d_out, int out_size) {
    const float* pred    = (const float*)d_in[0];
    const float* full    = (const float*)d_in[1];
    const float* partial = (const float*)d_in[2];
    const float* mu      = (const float*)d_in[3];
    const float* logvar  = (const float*)d_in[4];
    float* out = (float*)d_out;

    float *pf, *fp, *pp, *pt;
    cudaGetSymbolAddress((void**)&pf, g_pf);
    cudaGetSymbolAddress((void**)&fp, g_fp);
    cudaGetSymbolAddress((void**)&pp, g_part);
    cudaGetSymbolAddress((void**)&pt, g_partial);

    cudaMemsetAsync(pf, 0x7f, BB * NFULL * sizeof(float));
    cudaMemsetAsync(fp, 0x7f, BB * NFULL * sizeof(float));
    cudaMemsetAsync(pp, 0x7f, BB * NPART * sizeof(float));

    fused_rowmin_kernel<<<GRID, THREADS>>>(pred, full, partial, pf, fp, pp);

    reduce1_kernel<<<RBLKS, 256>>>(pf, fp, pp, mu, logvar, pt);
    reduce2_kernel<<<1, 128>>>(pt, out);
}

// round 12
// speedup vs baseline: 1.1709x; 1.1709x over previous
#include <cuda_runtime.h>
#include <math.h>

#define BB     8
#define NFULL  8192
#define NPART  2048
#define DLAT   512
#define EPSV   1e-12f

__device__ float g_pf[BB * NFULL];
__device__ float g_fp[BB * NFULL];
__device__ float g_part[BB * NPART];

constexpr int RBLKS = 120;
__device__ float g_partial[4 * RBLKS];

constexpr int THREADS = 256;              // 8 warps
constexpr int WARPS   = 8;
constexpr int Q       = 4;                // queries per thread (2 packed pairs)
constexpr int QP      = Q / 2;
constexpr int QPB     = THREADS * Q;      // 1024 queries per task
constexpr int CHUNK   = 512;              // refs per task

typedef unsigned long long u64;

__device__ __forceinline__ u64 pack2(float lo, float hi) {
    u64 r; asm("mov.b64 %0, {%1, %2};" : "=l"(r) : "f"(lo), "f"(hi)); return r;
}
__device__ __forceinline__ void unpack2(u64 v, float& lo, float& hi) {
    asm("mov.b64 {%0, %1}, %2;" : "=f"(lo), "=f"(hi) : "l"(v));
}
__device__ __forceinline__ u64 ffma2(u64 a, u64 b, u64 c) {
    u64 d; asm("fma.rn.f32x2 %0, %1, %2, %3;" : "=l"(d) : "l"(a), "l"(b), "l"(c)); return d;
}
__device__ __forceinline__ u64 fadd2(u64 a, u64 b) {
    u64 d; asm("add.rn.f32x2 %0, %1, %2;" : "=l"(d) : "l"(a), "l"(b)); return d;
}
// Warp-min of a NON-NEGATIVE float via integer redux (bit order == float order).
__device__ __forceinline__ float warp_min_pos(float v) {
    unsigned int r;
    asm("redux.sync.min.u32 %0, %1, 0xffffffff;"
        : "=r"(r) : "r"(__float_as_uint(v)));
    return __uint_as_float(r);
}

// ---------------------------------------------------------------------------
// Symmetric chamfer: tile (1024 pred-queries x 512 full-refs) computed once;
// row mins -> pf, col mins -> fp.  Fidelity tasks: rows only -> pp.
// s_ij = u_i + w_j - dot_ij >= 0
// ---------------------------------------------------------------------------
constexpr int RCK       = NFULL / CHUNK;             // 16
constexpr int CHAM_QT   = NFULL / QPB;               // 8
constexpr int FID_QT    = NPART / QPB;               // 2
constexpr int SYM_TASKS = CHAM_QT * RCK * BB;        // 1024
constexpr int FID_TASKS = FID_QT * RCK * BB;         // 256
constexpr int GRID      = SYM_TASKS + FID_TASKS;     // 1280

__global__ __launch_bounds__(THREADS)
void fused_rowmin_kernel(const float* __restrict__ pred,
                         const float* __restrict__ full,
                         const float* __restrict__ partial,
                         float* __restrict__ pf,
                         float* __restrict__ fp,
                         float* __restrict__ pp) {
    __shared__ ulonglong2 tA[CHUNK];            // (pack(x,x), pack(y,y))  8KB
    __shared__ ulonglong2 tB[CHUNK];            // (pack(z,z), pack(w,w))  8KB
    __shared__ float      colmin[WARPS][CHUNK]; // 16KB

    const int tid = threadIdx.x;
    const int wid = tid >> 5;
    const int lid = tid & 31;

    // ---- decode task ----
    const float *q, *r;
    float *rowout;
    bool sym;
    int b, ck, qt, Nq;
    int l = blockIdx.x;
    if (l < SYM_TASKS) {
        sym = true;
        b  = l >> 7;
        int rm = l & 127;
        ck = rm >> 3;
        qt = rm & 7;
        q = pred; r = full; rowout = pf; Nq = NFULL;
    } else {
        sym = false;
        l -= SYM_TASKS;
        b  = l >> 5;
        int rm = l & 31;
        ck = rm >> 1;
        qt = rm & 1;
        q = partial; r = pred; rowout = pp; Nq = NPART;
    }
    const int qbase = qt * QPB;
    const int rbase = ck * CHUNK;

    const float* qb = q + (size_t)b * Nq * 3;
    const float* rb = r + (size_t)b * NFULL * 3;

    // ---- tile load: dup-packed refs ----
    for (int j = tid; j < CHUNK; j += THREADS) {
        int rj = rbase + j;
        float x = rb[rj * 3 + 0];
        float y = rb[rj * 3 + 1];
        float z = rb[rj * 3 + 2];
        float w = 0.5f * (x * x + y * y + z * z);
        ulonglong2 a, bb;
        a.x  = pack2(x, x); a.y  = pack2(y, y);
        bb.x = pack2(z, z); bb.y = pack2(w, w);
        tA[j] = a;
        tB[j] = bb;
    }
    __syncthreads();

    // ---- per-thread queries: 2 packed pairs, negated coords + u = |q|^2/2 ----
    u64 nqx[QP], nqy[QP], nqz[QP], up[QP];
    float m0[QP], m1[QP];
    const float* qrow = qb + (size_t)(qbase + tid * Q) * 3;
#pragma unroll
    for (int k = 0; k < QP; k++) {
        float x0 = qrow[6 * k + 0], y0 = qrow[6 * k + 1], z0 = qrow[6 * k + 2];
        float x1 = qrow[6 * k + 3], y1 = qrow[6 * k + 4], z1 = qrow[6 * k + 5];
        nqx[k] = pack2(-x0, -x1);
        nqy[k] = pack2(-y0, -y1);
        nqz[k] = pack2(-z0, -z1);
        up[k]  = pack2(0.5f * (x0 * x0 + y0 * y0 + z0 * z0),
                       0.5f * (x1 * x1 + y1 * y1 + z1 * z1));
        m0[k]  = __int_as_float(0x7f800000);
        m1[k]  = __int_as_float(0x7f800000);
    }

    // ---- main loop ----
    if (sym) {
        // s = (u + w) - dot, 4 fma-ops per packed pair
#pragma unroll 4
        for (int j = 0; j < CHUNK; j++) {
            ulonglong2 A = tA[j];
            ulonglong2 B = tB[j];
            float s0[QP], s1[QP];
#pragma unroll
            for (int k = 0; k < QP; k++) {
                u64 v = ffma2(nqz[k], B.x, fadd2(B.y, up[k]));
                v = ffma2(nqy[k], A.y, v);
                v = ffma2(nqx[k], A.x, v);
                unpack2(v, s0[k], s1[k]);
                m0[k] = fminf(m0[k], s0[k]);
                m1[k] = fminf(m1[k], s1[k]);
            }
            float c = fminf(fminf(s0[0], s1[0]), fminf(s0[1], s1[1]));
            float cw = warp_min_pos(c);
            if (lid == 0) colmin[wid][j] = cw;
        }
    } else {
        // fid: t-form (w - dot), u added at writeback; 3 fma-ops per pair
#pragma unroll 4
        for (int j = 0; j < CHUNK; j++) {
            ulonglong2 A = tA[j];
            ulonglong2 B = tB[j];
#pragma unroll
            for (int k = 0; k < QP; k++) {
                u64 v = ffma2(nqz[k], B.x, B.y);
                v = ffma2(nqy[k], A.y, v);
                v = ffma2(nqx[k], A.x, v);
                float s0, s1;
                unpack2(v, s0, s1);
                m0[k] = fminf(m0[k], s0);
                m1[k] = fminf(m1[k], s1);
            }
        }
    }

    // ---- row writeback ----
#pragma unroll
    for (int k = 0; k < QP; k++) {
        float u0, u1;
        unpack2(up[k], u0, u1);
        int qi = qbase + tid * Q + 2 * k;
        // sym: m already = s_min; fid: m = t_min, add u back
        float a0 = sym ? m0[k] : (u0 + m0[k]);
        float a1 = sym ? m1[k] : (u1 + m1[k]);
        float s0 = fmaxf(a0 + a0, EPSV);
        float s1 = fmaxf(a1 + a1, EPSV);
        atomicMin((unsigned int*)&rowout[(size_t)b * Nq + qi],     __float_as_uint(s0));
        atomicMin((unsigned int*)&rowout[(size_t)b * Nq + qi + 1], __float_as_uint(s1));
    }

    // ---- col writeback (chamfer only): merge 8 warps ----
    if (sym) {
        __syncthreads();
        for (int j = tid; j < CHUNK; j += THREADS) {
            float v = fminf(
                fminf(fminf(colmin[0][j], colmin[1][j]),
                      fminf(colmin[2][j], colmin[3][j])),
                fminf(fminf(colmin[4][j], colmin[5][j]),
                      fminf(colmin[6][j], colmin[7][j])));
            float sq = fmaxf(v + v, EPSV);
            atomicMin((unsigned int*)&fp[(size_t)b * NFULL + rbase + j],
                      __float_as_uint(sq));
        }
    }
}

// ---------------------------------------------------------------------------
__global__ __launch_bounds__(256)
void reduce1_kernel(const float* __restrict__ pf,
                    const float* __restrict__ fp,
                    const float* __restrict__ pp,
                    const float* __restrict__ mu,
                    const float* __restrict__ lv,
                    float* __restrict__ partials) {
    const int tid    = threadIdx.x;
    const int stride = gridDim.x * blockDim.x;
    const int g      = blockIdx.x * blockDim.x + tid;

    float s_pf = 0.f, s_fp = 0.f, s_pp = 0.f, s_kl = 0.f;
    for (int i = g; i < BB * NFULL; i += stride) {
        s_pf += sqrtf(pf[i]);
        s_fp += sqrtf(fp[i]);
    }
    for (int i = g; i < BB * NPART; i += stride) s_pp += sqrtf(pp[i]);
    for (int i = g; i < BB * DLAT; i += stride) {
        float m = mu[i], l = lv[i];
        s_kl += 1.0f + l - m * m - expf(l);
    }

    __shared__ float sh[4][8];
#pragma unroll
    for (int off = 16; off > 0; off >>= 1) {
        s_pf += __shfl_down_sync(0xffffffffu, s_pf, off);
        s_fp += __shfl_down_sync(0xffffffffu, s_fp, off);
        s_pp += __shfl_down_sync(0xffffffffu, s_pp, off);
        s_kl += __shfl_down_sync(0xffffffffu, s_kl, off);
    }
    int wid = tid >> 5, lid = tid & 31;
    if (lid == 0) { sh[0][wid] = s_pf; sh[1][wid] = s_fp; sh[2][wid] = s_pp; sh[3][wid] = s_kl; }
    __syncthreads();

    if (tid < 4) {
        float acc = 0.f;
#pragma unroll
        for (int w = 0; w < 8; w++) acc += sh[tid][w];
        partials[tid * RBLKS + blockIdx.x] = acc;
    }
}

// ---------------------------------------------------------------------------
__global__ __launch_bounds__(128)
void reduce2_kernel(const float* __restrict__ partials,
                    float* __restrict__ out) {
    const int tid = threadIdx.x;
    const int wid = tid >> 5;
    const int lid = tid & 31;

    float s = 0.f;
    for (int i = lid; i < RBLKS; i += 32) s += partials[wid * RBLKS + i];
#pragma unroll
    for (int off = 16; off > 0; off >>= 1)
        s += __shfl_down_sync(0xffffffffu, s, off);

    __shared__ float sums[4];
    if (lid == 0) sums[wid] = s;
    __syncthreads();

    if (tid == 0) {
        float inv_nf = 1.0f / (float)(BB * NFULL);
        float cd  = 0.5f * (sums[0] + sums[1]) * inv_nf;
        float fid = sums[2] / (float)(BB * NPART);
        float kl  = -0.5f * sums[3] / (float)BB;
        float total = 1.0f * cd + 0.01f * kl + 0.5f * fid;
        out[0] = total;
        out[1] = cd;
        out[2] = kl;
        out[3] = fid;
    }
}

// ---------------------------------------------------------------------------
extern "C" void kernel_launch(void* const* d_in, const int* in_sizes, int n_in,
                              void* d_out, int out_size) {
    const float* pred    = (const float*)d_in[0];
    const float* full    = (const float*)d_in[1];
    const float* partial = (const float*)d_in[2];
    const float* mu      = (const float*)d_in[3];
    const float* logvar  = (const float*)d_in[4];
    float* out = (float*)d_out;

    float *pf, *fp, *pp, *pt;
    cudaGetSymbolAddress((void**)&pf, g_pf);
    cudaGetSymbolAddress((void**)&fp, g_fp);
    cudaGetSymbolAddress((void**)&pp, g_part);
    cudaGetSymbolAddress((void**)&pt, g_partial);

    cudaMemsetAsync(pf, 0x7f, BB * NFULL * sizeof(float));
    cudaMemsetAsync(fp, 0x7f, BB * NFULL * sizeof(float));
    cudaMemsetAsync(pp, 0x7f, BB * NPART * sizeof(float));

    fused_rowmin_kernel<<<GRID, THREADS>>>(pred, full, partial, pf, fp, pp);

    reduce1_kernel<<<RBLKS, 256>>>(pf, fp, pp, mu, logvar, pt);
    reduce2_kernel<<<1, 128>>>(pt, out);
}

// round 13
// speedup vs baseline: 1.2261x; 1.0472x over previous
#include <cuda_runtime.h>
#include <math.h>

#define BB     8
#define NFULL  8192
#define NPART  2048
#define DLAT   512
#define EPSV   1e-12f

// Single scratch: [pf | fp | pp]
constexpr int PF_OFF = 0;
constexpr int FP_OFF = BB * NFULL;
constexpr int PP_OFF = 2 * BB * NFULL;
constexpr int MIN_TOTAL = 2 * BB * NFULL + BB * NPART;
__device__ float g_min[MIN_TOTAL];

constexpr int RBLKS = 120;
__device__ float g_partial[4 * RBLKS];

constexpr int THREADS = 256;              // 8 warps
constexpr int WARPS   = 8;
constexpr int Q       = 4;                // queries per thread (2 packed pairs)
constexpr int QP      = Q / 2;
constexpr int QPB     = THREADS * Q;      // 1024 queries per task
constexpr int CHUNK   = 512;              // refs per task

typedef unsigned long long u64;

__device__ __forceinline__ u64 pack2(float lo, float hi) {
    u64 r; asm("mov.b64 %0, {%1, %2};" : "=l"(r) : "f"(lo), "f"(hi)); return r;
}
__device__ __forceinline__ void unpack2(u64 v, float& lo, float& hi) {
    asm("mov.b64 {%0, %1}, %2;" : "=f"(lo), "=f"(hi) : "l"(v));
}
__device__ __forceinline__ u64 ffma2(u64 a, u64 b, u64 c) {
    u64 d; asm("fma.rn.f32x2 %0, %1, %2, %3;" : "=l"(d) : "l"(a), "l"(b), "l"(c)); return d;
}
__device__ __forceinline__ u64 fadd2(u64 a, u64 b) {
    u64 d; asm("add.rn.f32x2 %0, %1, %2;" : "=l"(d) : "l"(a), "l"(b)); return d;
}
// Warp-min of a NON-NEGATIVE float via integer redux (bit order == float order).
__device__ __forceinline__ float warp_min_pos(float v) {
    unsigned int r;
    asm("redux.sync.min.u32 %0, %1, 0xffffffff;"
        : "=r"(r) : "r"(__float_as_uint(v)));
    return __uint_as_float(r);
}

// ---------------------------------------------------------------------------
constexpr int RCK       = NFULL / CHUNK;             // 16
constexpr int CHAM_QT   = NFULL / QPB;               // 8
constexpr int FID_QT    = NPART / QPB;               // 2
constexpr int SYM_TASKS = CHAM_QT * RCK * BB;        // 1024
constexpr int FID_TASKS = FID_QT * RCK * BB;         // 256
constexpr int GRID      = SYM_TASKS + FID_TASKS;     // 1280

__global__ __launch_bounds__(THREADS)
void fused_rowmin_kernel(const float* __restrict__ pred,
                         const float* __restrict__ full,
                         const float* __restrict__ partial,
                         float* __restrict__ gmin) {
    __shared__ ulonglong2 tA[CHUNK];            // (pack(x,x), pack(y,y))  8KB
    __shared__ ulonglong2 tB[CHUNK];            // (pack(z,z), pack(w,w))  8KB
    __shared__ float      colmin[WARPS][CHUNK]; // 16KB

    const int tid = threadIdx.x;
    const int wid = tid >> 5;
    const int lid = tid & 31;

    // ---- decode task ----
    const float *q, *r;
    float *rowout;
    bool sym;
    int b, ck, qt, Nq;
    int l = blockIdx.x;
    if (l < SYM_TASKS) {
        sym = true;
        b  = l >> 7;
        int rm = l & 127;
        ck = rm >> 3;
        qt = rm & 7;
        q = pred; r = full; rowout = gmin + PF_OFF; Nq = NFULL;
    } else {
        sym = false;
        l -= SYM_TASKS;
        b  = l >> 5;
        int rm = l & 31;
        ck = rm >> 1;
        qt = rm & 1;
        q = partial; r = pred; rowout = gmin + PP_OFF; Nq = NPART;
    }
    const int qbase = qt * QPB;
    const int rbase = ck * CHUNK;

    const float* qb = q + (size_t)b * Nq * 3;
    const float* rb = r + (size_t)b * NFULL * 3;

    // ---- tile load: dup-packed refs ----
    for (int j = tid; j < CHUNK; j += THREADS) {
        int rj = rbase + j;
        float x = rb[rj * 3 + 0];
        float y = rb[rj * 3 + 1];
        float z = rb[rj * 3 + 2];
        float w = 0.5f * (x * x + y * y + z * z);
        ulonglong2 a, bb;
        a.x  = pack2(x, x); a.y  = pack2(y, y);
        bb.x = pack2(z, z); bb.y = pack2(w, w);
        tA[j] = a;
        tB[j] = bb;
    }
    __syncthreads();

    // ---- per-thread queries: 2 packed pairs ----
    u64 nqx[QP], nqy[QP], nqz[QP], up[QP];
    float m0[QP], m1[QP];
    const float* qrow = qb + (size_t)(qbase + tid * Q) * 3;
#pragma unroll
    for (int k = 0; k < QP; k++) {
        float x0 = qrow[6 * k + 0], y0 = qrow[6 * k + 1], z0 = qrow[6 * k + 2];
        float x1 = qrow[6 * k + 3], y1 = qrow[6 * k + 4], z1 = qrow[6 * k + 5];
        nqx[k] = pack2(-x0, -x1);
        nqy[k] = pack2(-y0, -y1);
        nqz[k] = pack2(-z0, -z1);
        up[k]  = pack2(0.5f * (x0 * x0 + y0 * y0 + z0 * z0),
                       0.5f * (x1 * x1 + y1 * y1 + z1 * z1));
        m0[k]  = __int_as_float(0x7f800000);
        m1[k]  = __int_as_float(0x7f800000);
    }

    if (sym) {
        // s = (u + w) - dot; 4-j groups: batch 4 independent reduxes + STS.128
        for (int j4 = 0; j4 < CHUNK; j4 += 4) {
            float c[4];
#pragma unroll
            for (int jj = 0; jj < 4; jj++) {
                ulonglong2 A = tA[j4 + jj];
                ulonglong2 B = tB[j4 + jj];
                float s0[QP], s1[QP];
#pragma unroll
                for (int k = 0; k < QP; k++) {
                    u64 v = ffma2(nqz[k], B.x, fadd2(B.y, up[k]));
                    v = ffma2(nqy[k], A.y, v);
                    v = ffma2(nqx[k], A.x, v);
                    unpack2(v, s0[k], s1[k]);
                    m0[k] = fminf(m0[k], s0[k]);
                    m1[k] = fminf(m1[k], s1[k]);
                }
                c[jj] = fminf(fminf(s0[0], s1[0]), fminf(s0[1], s1[1]));
            }
            // 4 independent warp reduxes (pipeline), one STS.128
            float r0 = warp_min_pos(c[0]);
            float r1 = warp_min_pos(c[1]);
            float r2 = warp_min_pos(c[2]);
            float r3 = warp_min_pos(c[3]);
            if (lid == 0)
                *reinterpret_cast<float4*>(&colmin[wid][j4]) =
                    make_float4(r0, r1, r2, r3);
        }
    } else {
        // fid: t-form (w - dot), u added at writeback
#pragma unroll 4
        for (int j = 0; j < CHUNK; j++) {
            ulonglong2 A = tA[j];
            ulonglong2 B = tB[j];
#pragma unroll
            for (int k = 0; k < QP; k++) {
                u64 v = ffma2(nqz[k], B.x, B.y);
                v = ffma2(nqy[k], A.y, v);
                v = ffma2(nqx[k], A.x, v);
                float s0, s1;
                unpack2(v, s0, s1);
                m0[k] = fminf(m0[k], s0);
                m1[k] = fminf(m1[k], s1);
            }
        }
    }

    // ---- row writeback ----
#pragma unroll
    for (int k = 0; k < QP; k++) {
        float u0, u1;
        unpack2(up[k], u0, u1);
        int qi = qbase + tid * Q + 2 * k;
        float a0 = sym ? m0[k] : (u0 + m0[k]);
        float a1 = sym ? m1[k] : (u1 + m1[k]);
        float s0 = fmaxf(a0 + a0, EPSV);
        float s1 = fmaxf(a1 + a1, EPSV);
        atomicMin((unsigned int*)&rowout[(size_t)b * Nq + qi],     __float_as_uint(s0));
        atomicMin((unsigned int*)&rowout[(size_t)b * Nq + qi + 1], __float_as_uint(s1));
    }

    // ---- col writeback (chamfer only): merge 8 warps ----
    if (sym) {
        __syncthreads();
        float* fpout = gmin + FP_OFF;
        for (int j = tid; j < CHUNK; j += THREADS) {
            float v = fminf(
                fminf(fminf(colmin[0][j], colmin[1][j]),
                      fminf(colmin[2][j], colmin[3][j])),
                fminf(fminf(colmin[4][j], colmin[5][j]),
                      fminf(colmin[6][j], colmin[7][j])));
            float sq = fmaxf(v + v, EPSV);
            atomicMin((unsigned int*)&fpout[(size_t)b * NFULL + rbase + j],
                      __float_as_uint(sq));
        }
    }
}

// ---------------------------------------------------------------------------
__global__ __launch_bounds__(256)
void reduce1_kernel(const float* __restrict__ gmin,
                    const float* __restrict__ mu,
                    const float* __restrict__ lv,
                    float* __restrict__ partials) {
    const int tid    = threadIdx.x;
    const int stride = gridDim.x * blockDim.x;
    const int g      = blockIdx.x * blockDim.x + tid;

    const float* pf = gmin + PF_OFF;
    const float* fp = gmin + FP_OFF;
    const float* pp = gmin + PP_OFF;

    float s_pf = 0.f, s_fp = 0.f, s_pp = 0.f, s_kl = 0.f;
    for (int i = g; i < BB * NFULL; i += stride) {
        s_pf += sqrtf(pf[i]);
        s_fp += sqrtf(fp[i]);
    }
    for (int i = g; i < BB * NPART; i += stride) s_pp += sqrtf(pp[i]);
    for (int i = g; i < BB * DLAT; i += stride) {
        float m = mu[i], l = lv[i];
        s_kl += 1.0f + l - m * m - expf(l);
    }

    __shared__ float sh[4][8];
#pragma unroll
    for (int off = 16; off > 0; off >>= 1) {
        s_pf += __shfl_down_sync(0xffffffffu, s_pf, off);
        s_fp += __shfl_down_sync(0xffffffffu, s_fp, off);
        s_pp += __shfl_down_sync(0xffffffffu, s_pp, off);
        s_kl += __shfl_down_sync(0xffffffffu, s_kl, off);
    }
    int wid = tid >> 5, lid = tid & 31;
    if (lid == 0) { sh[0][wid] = s_pf; sh[1][wid] = s_fp; sh[2][wid] = s_pp; sh[3][wid] = s_kl; }
    __syncthreads();

    if (tid < 4) {
        float acc = 0.f;
#pragma unroll
        for (int w = 0; w < 8; w++) acc += sh[tid][w];
        partials[tid * RBLKS + blockIdx.x] = acc;
    }
}

// ---------------------------------------------------------------------------
__global__ __launch_bounds__(128)
void reduce2_kernel(const float* __restrict__ partials,
                    float* __restrict__ out) {
    const int tid = threadIdx.x;
    const int wid = tid >> 5;
    const int lid = tid & 31;

    float s = 0.f;
    for (int i = lid; i < RBLKS; i += 32) s += partials[wid * RBLKS + i];
#pragma unroll
    for (int off = 16; off > 0; off >>= 1)
        s += __shfl_down_sync(0xffffffffu, s, off);

    __shared__ float sums[4];
    if (lid == 0) sums[wid] = s;
    __syncthreads();

    if (tid == 0) {
        float inv_nf = 1.0f / (float)(BB * NFULL);
        float cd  = 0.5f * (sums[0] + sums[1]) * inv_nf;
        float fid = sums[2] / (float)(BB * NPART);
        float kl  = -0.5f * sums[3] / (float)BB;
        float total = 1.0f * cd + 0.01f * kl + 0.5f * fid;
        out[0] = total;
        out[1] = cd;
        out[2] = kl;
        out[3] = fid;
    }
}

// ---------------------------------------------------------------------------
extern "C" void kernel_launch(void* const* d_in, const int* in_sizes, int n_in,
                              void* d_out, int out_size) {
    const float* pred    = (const float*)d_in[0];
    const float* full    = (const float*)d_in[1];
    const float* partial = (const float*)d_in[2];
    const float* mu      = (const float*)d_in[3];
    const float* logvar  = (const float*)d_in[4];
    float* out = (float*)d_out;

    float *gm, *pt;
    cudaGetSymbolAddress((void**)&gm, g_min);
    cudaGetSymbolAddress((void**)&pt, g_partial);

    // One memset: 0x7f7f7f7f = 3.39e38 > any real squared distance.
    cudaMemsetAsync(gm, 0x7f, MIN_TOTAL * sizeof(float));

    fused_rowmin_kernel<<<GRID, THREADS>>>(pred, full, partial, gm);

    reduce1_kernel<<<RBLKS, 256>>>(gm, mu, logvar, pt);
    reduce2_kernel<<<1, 128>>>(pt, out);
}

// round 14
// speedup vs baseline: 1.2476x; 1.0175x over previous
#include <cuda_runtime.h>
#include <math.h>

#define BB     8
#define NFULL  8192
#define NPART  2048
#define DLAT   512
#define EPSV   1e-12f

// Single scratch: [pf | fp | pp]
constexpr int PF_OFF = 0;
constexpr int FP_OFF = BB * NFULL;
constexpr int PP_OFF = 2 * BB * NFULL;
constexpr int MIN_TOTAL = 2 * BB * NFULL + BB * NPART;
__device__ float g_min[MIN_TOTAL];

constexpr int RBLKS = 120;
__device__ float g_partial[4 * RBLKS];

constexpr int THREADS = 256;              // 8 warps
constexpr int WARPS   = 8;
constexpr int Q       = 4;                // queries per thread (2 packed pairs)
constexpr int QP      = Q / 2;
constexpr int QPB     = THREADS * Q;      // 1024 queries per task
constexpr int CHUNK   = 512;              // refs per task

typedef unsigned long long u64;

__device__ __forceinline__ u64 pack2(float lo, float hi) {
    u64 r; asm("mov.b64 %0, {%1, %2};" : "=l"(r) : "f"(lo), "f"(hi)); return r;
}
__device__ __forceinline__ void unpack2(u64 v, float& lo, float& hi) {
    asm("mov.b64 {%0, %1}, %2;" : "=f"(lo), "=f"(hi) : "l"(v));
}
__device__ __forceinline__ u64 ffma2(u64 a, u64 b, u64 c) {
    u64 d; asm("fma.rn.f32x2 %0, %1, %2, %3;" : "=l"(d) : "l"(a), "l"(b), "l"(c)); return d;
}
__device__ __forceinline__ u64 fadd2(u64 a, u64 b) {
    u64 d; asm("add.rn.f32x2 %0, %1, %2;" : "=l"(d) : "l"(a), "l"(b)); return d;
}
// Warp-min of a NON-NEGATIVE float via integer redux (bit order == float order).
__device__ __forceinline__ float warp_min_pos(float v) {
    unsigned int r;
    asm("redux.sync.min.u32 %0, %1, 0xffffffff;"
        : "=r"(r) : "r"(__float_as_uint(v)));
    return __uint_as_float(r);
}

// ---------------------------------------------------------------------------
constexpr int RCK       = NFULL / CHUNK;             // 16
constexpr int CHAM_QT   = NFULL / QPB;               // 8
constexpr int FID_QT    = NPART / QPB;               // 2
constexpr int SYM_TASKS = CHAM_QT * RCK * BB;        // 1024
constexpr int FID_TASKS = FID_QT * RCK * BB;         // 256
constexpr int GRID      = SYM_TASKS + FID_TASKS;     // 1280

__global__ __launch_bounds__(THREADS)
void fused_rowmin_kernel(const float* __restrict__ pred,
                         const float* __restrict__ full,
                         const float* __restrict__ partial,
                         float* __restrict__ gmin) {
    __shared__ ulonglong2 tA[CHUNK];            // (pack(x,x), pack(y,y))  8KB
    __shared__ ulonglong2 tB[CHUNK];            // (pack(z,z), pack(w,w))  8KB
    __shared__ float      colmin[WARPS][CHUNK]; // 16KB

    const int tid = threadIdx.x;
    const int wid = tid >> 5;
    const int lid = tid & 31;

    // ---- decode task ----
    const float *q, *r;
    float *rowout;
    bool sym;
    int b, ck, qt, Nq;
    int l = blockIdx.x;
    if (l < SYM_TASKS) {
        sym = true;
        b  = l >> 7;
        int rm = l & 127;
        ck = rm >> 3;
        qt = rm & 7;
        q = pred; r = full; rowout = gmin + PF_OFF; Nq = NFULL;
    } else {
        sym = false;
        l -= SYM_TASKS;
        b  = l >> 5;
        int rm = l & 31;
        ck = rm >> 1;
        qt = rm & 1;
        q = partial; r = pred; rowout = gmin + PP_OFF; Nq = NPART;
    }
    const int qbase = qt * QPB;
    const int rbase = ck * CHUNK;

    const float* qb = q + (size_t)b * Nq * 3;
    const float* rb = r + (size_t)b * NFULL * 3;

    // ---- tile load: dup-packed refs ----
    for (int j = tid; j < CHUNK; j += THREADS) {
        int rj = rbase + j;
        float x = rb[rj * 3 + 0];
        float y = rb[rj * 3 + 1];
        float z = rb[rj * 3 + 2];
        float w = 0.5f * (x * x + y * y + z * z);
        ulonglong2 a, bb;
        a.x  = pack2(x, x); a.y  = pack2(y, y);
        bb.x = pack2(z, z); bb.y = pack2(w, w);
        tA[j] = a;
        tB[j] = bb;
    }
    __syncthreads();

    // ---- per-thread queries: 2 packed pairs ----
    u64 nqx[QP], nqy[QP], nqz[QP], up[QP];
    float m0[QP], m1[QP];
    const float* qrow = qb + (size_t)(qbase + tid * Q) * 3;
#pragma unroll
    for (int k = 0; k < QP; k++) {
        float x0 = qrow[6 * k + 0], y0 = qrow[6 * k + 1], z0 = qrow[6 * k + 2];
        float x1 = qrow[6 * k + 3], y1 = qrow[6 * k + 4], z1 = qrow[6 * k + 5];
        nqx[k] = pack2(-x0, -x1);
        nqy[k] = pack2(-y0, -y1);
        nqz[k] = pack2(-z0, -z1);
        up[k]  = pack2(0.5f * (x0 * x0 + y0 * y0 + z0 * z0),
                       0.5f * (x1 * x1 + y1 * y1 + z1 * z1));
        m0[k]  = __int_as_float(0x7f800000);
        m1[k]  = __int_as_float(0x7f800000);
    }

    if (sym) {
        // s = (u + w) - dot; 8-j groups: 8 pipelined reduxes + 2x STS.128
        for (int j8 = 0; j8 < CHUNK; j8 += 8) {
            float c[8];
#pragma unroll
            for (int jj = 0; jj < 8; jj++) {
                ulonglong2 A = tA[j8 + jj];
                ulonglong2 B = tB[j8 + jj];
                float s0[QP], s1[QP];
#pragma unroll
                for (int k = 0; k < QP; k++) {
                    u64 v = ffma2(nqz[k], B.x, fadd2(B.y, up[k]));
                    v = ffma2(nqy[k], A.y, v);
                    v = ffma2(nqx[k], A.x, v);
                    unpack2(v, s0[k], s1[k]);
                    m0[k] = fminf(m0[k], s0[k]);
                    m1[k] = fminf(m1[k], s1[k]);
                }
                c[jj] = fminf(fminf(s0[0], s1[0]), fminf(s0[1], s1[1]));
            }
            // 8 independent warp reduxes (pipeline through the redux unit)
            float r0 = warp_min_pos(c[0]);
            float r1 = warp_min_pos(c[1]);
            float r2 = warp_min_pos(c[2]);
            float r3 = warp_min_pos(c[3]);
            float r4 = warp_min_pos(c[4]);
            float r5 = warp_min_pos(c[5]);
            float r6 = warp_min_pos(c[6]);
            float r7 = warp_min_pos(c[7]);
            if (lid == 0) {
                *reinterpret_cast<float4*>(&colmin[wid][j8])     = make_float4(r0, r1, r2, r3);
                *reinterpret_cast<float4*>(&colmin[wid][j8 + 4]) = make_float4(r4, r5, r6, r7);
            }
        }
    } else {
        // fid: t-form (w - dot), u added at writeback
#pragma unroll 8
        for (int j = 0; j < CHUNK; j++) {
            ulonglong2 A = tA[j];
            ulonglong2 B = tB[j];
#pragma unroll
            for (int k = 0; k < QP; k++) {
                u64 v = ffma2(nqz[k], B.x, B.y);
                v = ffma2(nqy[k], A.y, v);
                v = ffma2(nqx[k], A.x, v);
                float s0, s1;
                unpack2(v, s0, s1);
                m0[k] = fminf(m0[k], s0);
                m1[k] = fminf(m1[k], s1);
            }
        }
    }

    // ---- row writeback ----
#pragma unroll
    for (int k = 0; k < QP; k++) {
        float u0, u1;
        unpack2(up[k], u0, u1);
        int qi = qbase + tid * Q + 2 * k;
        float a0 = sym ? m0[k] : (u0 + m0[k]);
        float a1 = sym ? m1[k] : (u1 + m1[k]);
        float s0 = fmaxf(a0 + a0, EPSV);
        float s1 = fmaxf(a1 + a1, EPSV);
        atomicMin((unsigned int*)&rowout[(size_t)b * Nq + qi],     __float_as_uint(s0));
        atomicMin((unsigned int*)&rowout[(size_t)b * Nq + qi + 1], __float_as_uint(s1));
    }

    // ---- col writeback (chamfer only): merge 8 warps ----
    if (sym) {
        __syncthreads();
        float* fpout = gmin + FP_OFF;
        for (int j = tid; j < CHUNK; j += THREADS) {
            float v = fminf(
                fminf(fminf(colmin[0][j], colmin[1][j]),
                      fminf(colmin[2][j], colmin[3][j])),
                fminf(fminf(colmin[4][j], colmin[5][j]),
                      fminf(colmin[6][j], colmin[7][j])));
            float sq = fmaxf(v + v, EPSV);
            atomicMin((unsigned int*)&fpout[(size_t)b * NFULL + rbase + j],
                      __float_as_uint(sq));
        }
    }
}

// ---------------------------------------------------------------------------
__global__ __launch_bounds__(256)
void reduce1_kernel(const float* __restrict__ gmin,
                    const float* __restrict__ mu,
                    const float* __restrict__ lv,
                    float* __restrict__ partials) {
    const int tid    = threadIdx.x;
    const int stride = gridDim.x * blockDim.x;
    const int g      = blockIdx.x * blockDim.x + tid;

    const float* pf = gmin + PF_OFF;
    const float* fp = gmin + FP_OFF;
    const float* pp = gmin + PP_OFF;

    float s_pf = 0.f, s_fp = 0.f, s_pp = 0.f, s_kl = 0.f;
    for (int i = g; i < BB * NFULL; i += stride) {
        s_pf += sqrtf(pf[i]);
        s_fp += sqrtf(fp[i]);
    }
    for (int i = g; i < BB * NPART; i += stride) s_pp += sqrtf(pp[i]);
    for (int i = g; i < BB * DLAT; i += stride) {
        float m = mu[i], l = lv[i];
        s_kl += 1.0f + l - m * m - expf(l);
    }

    __shared__ float sh[4][8];
#pragma unroll
    for (int off = 16; off > 0; off >>= 1) {
        s_pf += __shfl_down_sync(0xffffffffu, s_pf, off);
        s_fp += __shfl_down_sync(0xffffffffu, s_fp, off);
        s_pp += __shfl_down_sync(0xffffffffu, s_pp, off);
        s_kl += __shfl_down_sync(0xffffffffu, s_kl, off);
    }
    int wid = tid >> 5, lid = tid & 31;
    if (lid == 0) { sh[0][wid] = s_pf; sh[1][wid] = s_fp; sh[2][wid] = s_pp; sh[3][wid] = s_kl; }
    __syncthreads();

    if (tid < 4) {
        float acc = 0.f;
#pragma unroll
        for (int w = 0; w < 8; w++) acc += sh[tid][w];
        partials[tid * RBLKS + blockIdx.x] = acc;
    }
}

// ---------------------------------------------------------------------------
__global__ __launch_bounds__(128)
void reduce2_kernel(const float* __restrict__ partials,
                    float* __restrict__ out) {
    const int tid = threadIdx.x;
    const int wid = tid >> 5;
    const int lid = tid & 31;

    float s = 0.f;
    for (int i = lid; i < RBLKS; i += 32) s += partials[wid * RBLKS + i];
#pragma unroll
    for (int off = 16; off > 0; off >>= 1)
        s += __shfl_down_sync(0xffffffffu, s, off);

    __shared__ float sums[4];
    if (lid == 0) sums[wid] = s;
    __syncthreads();

    if (tid == 0) {
        float inv_nf = 1.0f / (float)(BB * NFULL);
        float cd  = 0.5f * (sums[0] + sums[1]) * inv_nf;
        float fid = sums[2] / (float)(BB * NPART);
        float kl  = -0.5f * sums[3] / (float)BB;
        float total = 1.0f * cd + 0.01f * kl + 0.5f * fid;
        out[0] = total;
        out[1] = cd;
        out[2] = kl;
        out[3] = fid;
    }
}

// ---------------------------------------------------------------------------
extern "C" void kernel_launch(void* const* d_in, const int* in_sizes, int n_in,
                              void* d_out, int out_size) {
    const float* pred    = (const float*)d_in[0];
    const float* full    = (const float*)d_in[1];
    const float* partial = (const float*)d_in[2];
    const float* mu      = (const float*)d_in[3];
    const float* logvar  = (const float*)d_in[4];
    float* out = (float*)d_out;

    float *gm, *pt;
    cudaGetSymbolAddress((void**)&gm, g_min);
    cudaGetSymbolAddress((void**)&pt, g_partial);

    // One memset: 0x7f7f7f7f = 3.39e38 > any real squared distance.
    cudaMemsetAsync(gm, 0x7f, MIN_TOTAL * sizeof(float));

    fused_rowmin_kernel<<<GRID, THREADS>>>(pred, full, partial, gm);

    reduce1_kernel<<<RBLKS, 256>>>(gm, mu, logvar, pt);
    reduce2_kernel<<<1, 128>>>(pt, out);
}

// round 15
// speedup vs baseline: 1.2526x; 1.0040x over previous
#include <cuda_runtime.h>
#include <math.h>

#define BB     8
#define NFULL  8192
#define NPART  2048
#define DLAT   512
#define EPSV   1e-12f

// Single scratch: [pf | fp | pp]
constexpr int PF_OFF = 0;
constexpr int FP_OFF = BB * NFULL;
constexpr int PP_OFF = 2 * BB * NFULL;
constexpr int MIN_TOTAL = 2 * BB * NFULL + BB * NPART;
__device__ float g_min[MIN_TOTAL];

constexpr int RBLKS = 120;
__device__ float g_partial[4 * RBLKS];

constexpr int THREADS = 256;              // 8 warps
constexpr int WARPS   = 8;
constexpr int Q       = 8;                // queries per thread (4 packed pairs)
constexpr int QP      = Q / 2;            // 4
constexpr int QPB     = THREADS * Q;      // 2048 queries per task
constexpr int CHUNK   = 256;              // refs per task

typedef unsigned long long u64;

__device__ __forceinline__ u64 pack2(float lo, float hi) {
    u64 r; asm("mov.b64 %0, {%1, %2};" : "=l"(r) : "f"(lo), "f"(hi)); return r;
}
__device__ __forceinline__ void unpack2(u64 v, float& lo, float& hi) {
    asm("mov.b64 {%0, %1}, %2;" : "=f"(lo), "=f"(hi) : "l"(v));
}
__device__ __forceinline__ u64 ffma2(u64 a, u64 b, u64 c) {
    u64 d; asm("fma.rn.f32x2 %0, %1, %2, %3;" : "=l"(d) : "l"(a), "l"(b), "l"(c)); return d;
}
__device__ __forceinline__ u64 fadd2(u64 a, u64 b) {
    u64 d; asm("add.rn.f32x2 %0, %1, %2;" : "=l"(d) : "l"(a), "l"(b)); return d;
}
// Warp-min of a NON-NEGATIVE float via integer redux (bit order == float order).
__device__ __forceinline__ float warp_min_pos(float v) {
    unsigned int r;
    asm("redux.sync.min.u32 %0, %1, 0xffffffff;"
        : "=r"(r) : "r"(__float_as_uint(v)));
    return __uint_as_float(r);
}

// ---------------------------------------------------------------------------
// Task geometry: QPB=2048, CHUNK=256.
// sym:  (8192/2048)=4 qtiles x 32 chunks x 8 batches = 1024 tasks
// fid:  (2048/2048)=1 qtile  x 32 chunks x 8 batches = 256 tasks
// ---------------------------------------------------------------------------
constexpr int RCK       = NFULL / CHUNK;             // 32
constexpr int CHAM_QT   = NFULL / QPB;               // 4
constexpr int SYM_TASKS = CHAM_QT * RCK * BB;        // 1024
constexpr int FID_TASKS = 1 * RCK * BB;              // 256
constexpr int GRID      = SYM_TASKS + FID_TASKS;     // 1280

__global__ __launch_bounds__(THREADS)
void fused_rowmin_kernel(const float* __restrict__ pred,
                         const float* __restrict__ full,
                         const float* __restrict__ partial,
                         float* __restrict__ gmin) {
    __shared__ ulonglong2 tA[CHUNK];            // (pack(x,x), pack(y,y))  4KB
    __shared__ ulonglong2 tB[CHUNK];            // (pack(z,z), pack(w,w))  4KB
    __shared__ float      colmin[WARPS][CHUNK]; // 8KB

    const int tid = threadIdx.x;
    const int wid = tid >> 5;
    const int lid = tid & 31;

    // ---- decode task ----
    const float *q, *r;
    float *rowout;
    bool sym;
    int b, ck, qt, Nq;
    int l = blockIdx.x;
    if (l < SYM_TASKS) {
        sym = true;
        b  = l >> 7;            // /128 (4 qtiles x 32 chunks)
        int rm = l & 127;
        ck = rm >> 2;           // 0..31
        qt = rm & 3;            // 0..3
        q = pred; r = full; rowout = gmin + PF_OFF; Nq = NFULL;
    } else {
        sym = false;
        l -= SYM_TASKS;
        b  = l >> 5;            // /32
        ck = l & 31;            // 0..31
        qt = 0;
        q = partial; r = pred; rowout = gmin + PP_OFF; Nq = NPART;
    }
    const int qbase = qt * QPB;
    const int rbase = ck * CHUNK;

    const float* qb = q + (size_t)b * Nq * 3;
    const float* rb = r + (size_t)b * NFULL * 3;

    // ---- tile load: dup-packed refs ----
    for (int j = tid; j < CHUNK; j += THREADS) {
        int rj = rbase + j;
        float x = rb[rj * 3 + 0];
        float y = rb[rj * 3 + 1];
        float z = rb[rj * 3 + 2];
        float w = 0.5f * (x * x + y * y + z * z);
        ulonglong2 a, bb;
        a.x  = pack2(x, x); a.y  = pack2(y, y);
        bb.x = pack2(z, z); bb.y = pack2(w, w);
        tA[j] = a;
        tB[j] = bb;
    }
    __syncthreads();

    // ---- per-thread queries: 4 packed pairs ----
    u64 nqx[QP], nqy[QP], nqz[QP], up[QP];
    float m0[QP], m1[QP];
    const float* qrow = qb + (size_t)(qbase + tid * Q) * 3;
#pragma unroll
    for (int k = 0; k < QP; k++) {
        float x0 = qrow[6 * k + 0], y0 = qrow[6 * k + 1], z0 = qrow[6 * k + 2];
        float x1 = qrow[6 * k + 3], y1 = qrow[6 * k + 4], z1 = qrow[6 * k + 5];
        nqx[k] = pack2(-x0, -x1);
        nqy[k] = pack2(-y0, -y1);
        nqz[k] = pack2(-z0, -z1);
        up[k]  = pack2(0.5f * (x0 * x0 + y0 * y0 + z0 * z0),
                       0.5f * (x1 * x1 + y1 * y1 + z1 * z1));
        m0[k]  = __int_as_float(0x7f800000);
        m1[k]  = __int_as_float(0x7f800000);
    }

    if (sym) {
        // s = (u + w) - dot; 4-j groups: 4 pipelined reduxes + STS.128
        for (int j4 = 0; j4 < CHUNK; j4 += 4) {
            float c[4];
#pragma unroll
            for (int jj = 0; jj < 4; jj++) {
                ulonglong2 A = tA[j4 + jj];
                ulonglong2 B = tB[j4 + jj];
                float cc = __int_as_float(0x7f800000);
#pragma unroll
                for (int k = 0; k < QP; k++) {
                    u64 v = ffma2(nqz[k], B.x, fadd2(B.y, up[k]));
                    v = ffma2(nqy[k], A.y, v);
                    v = ffma2(nqx[k], A.x, v);
                    float s0, s1;
                    unpack2(v, s0, s1);
                    m0[k] = fminf(m0[k], s0);
                    m1[k] = fminf(m1[k], s1);
                    cc = fminf(cc, fminf(s0, s1));
                }
                c[jj] = cc;
            }
            float r0 = warp_min_pos(c[0]);
            float r1 = warp_min_pos(c[1]);
            float r2 = warp_min_pos(c[2]);
            float r3 = warp_min_pos(c[3]);
            if (lid == 0)
                *reinterpret_cast<float4*>(&colmin[wid][j4]) =
                    make_float4(r0, r1, r2, r3);
        }
    } else {
        // fid: t-form (w - dot), u added at writeback
#pragma unroll 4
        for (int j = 0; j < CHUNK; j++) {
            ulonglong2 A = tA[j];
            ulonglong2 B = tB[j];
#pragma unroll
            for (int k = 0; k < QP; k++) {
                u64 v = ffma2(nqz[k], B.x, B.y);
                v = ffma2(nqy[k], A.y, v);
                v = ffma2(nqx[k], A.x, v);
                float s0, s1;
                unpack2(v, s0, s1);
                m0[k] = fminf(m0[k], s0);
                m1[k] = fminf(m1[k], s1);
            }
        }
    }

    // ---- row writeback ----
#pragma unroll
    for (int k = 0; k < QP; k++) {
        float u0, u1;
        unpack2(up[k], u0, u1);
        int qi = qbase + tid * Q + 2 * k;
        float a0 = sym ? m0[k] : (u0 + m0[k]);
        float a1 = sym ? m1[k] : (u1 + m1[k]);
        float s0 = fmaxf(a0 + a0, EPSV);
        float s1 = fmaxf(a1 + a1, EPSV);
        atomicMin((unsigned int*)&rowout[(size_t)b * Nq + qi],     __float_as_uint(s0));
        atomicMin((unsigned int*)&rowout[(size_t)b * Nq + qi + 1], __float_as_uint(s1));
    }

    // ---- col writeback (chamfer only): merge 8 warps ----
    if (sym) {
        __syncthreads();
        float* fpout = gmin + FP_OFF;
        for (int j = tid; j < CHUNK; j += THREADS) {
            float v = fminf(
                fminf(fminf(colmin[0][j], colmin[1][j]),
                      fminf(colmin[2][j], colmin[3][j])),
                fminf(fminf(colmin[4][j], colmin[5][j]),
                      fminf(colmin[6][j], colmin[7][j])));
            float sq = fmaxf(v + v, EPSV);
            atomicMin((unsigned int*)&fpout[(size_t)b * NFULL + rbase + j],
                      __float_as_uint(sq));
        }
    }
}

// ---------------------------------------------------------------------------
__global__ __launch_bounds__(256)
void reduce1_kernel(const float* __restrict__ gmin,
                    const float* __restrict__ mu,
                    const float* __restrict__ lv,
                    float* __restrict__ partials) {
    const int tid    = threadIdx.x;
    const int stride = gridDim.x * blockDim.x;
    const int g      = blockIdx.x * blockDim.x + tid;

    const float* pf = gmin + PF_OFF;
    const float* fp = gmin + FP_OFF;
    const float* pp = gmin + PP_OFF;

    float s_pf = 0.f, s_fp = 0.f, s_pp = 0.f, s_kl = 0.f;
    for (int i = g; i < BB * NFULL; i += stride) {
        s_pf += sqrtf(pf[i]);
        s_fp += sqrtf(fp[i]);
    }
    for (int i = g; i < BB * NPART; i += stride) s_pp += sqrtf(pp[i]);
    for (int i = g; i < BB * DLAT; i += stride) {
        float m = mu[i], l = lv[i];
        s_kl += 1.0f + l - m * m - expf(l);
    }

    __shared__ float sh[4][8];
#pragma unroll
    for (int off = 16; off > 0; off >>= 1) {
        s_pf += __shfl_down_sync(0xffffffffu, s_pf, off);
        s_fp += __shfl_down_sync(0xffffffffu, s_fp, off);
        s_pp += __shfl_down_sync(0xffffffffu, s_pp, off);
        s_kl += __shfl_down_sync(0xffffffffu, s_kl, off);
    }
    int wid = tid >> 5, lid = tid & 31;
    if (lid == 0) { sh[0][wid] = s_pf; sh[1][wid] = s_fp; sh[2][wid] = s_pp; sh[3][wid] = s_kl; }
    __syncthreads();

    if (tid < 4) {
        float acc = 0.f;
#pragma unroll
        for (int w = 0; w < 8; w++) acc += sh[tid][w];
        partials[tid * RBLKS + blockIdx.x] = acc;
    }
}

// ---------------------------------------------------------------------------
__global__ __launch_bounds__(128)
void reduce2_kernel(const float* __restrict__ partials,
                    float* __restrict__ out) {
    const int tid = threadIdx.x;
    const int wid = tid >> 5;
    const int lid = tid & 31;

    float s = 0.f;
    for (int i = lid; i < RBLKS; i += 32) s += partials[wid * RBLKS + i];
#pragma unroll
    for (int off = 16; off > 0; off >>= 1)
        s += __shfl_down_sync(0xffffffffu, s, off);

    __shared__ float sums[4];
    if (lid == 0) sums[wid] = s;
    __syncthreads();

    if (tid == 0) {
        float inv_nf = 1.0f / (float)(BB * NFULL);
        float cd  = 0.5f * (sums[0] + sums[1]) * inv_nf;
        float fid = sums[2] / (float)(BB * NPART);
        float kl  = -0.5f * sums[3] / (float)BB;
        float total = 1.0f * cd + 0.01f * kl + 0.5f * fid;
        out[0] = total;
        out[1] = cd;
        out[2] = kl;
        out[3] = fid;
    }
}

// ---------------------------------------------------------------------------
extern "C" void kernel_launch(void* const* d_in, const int* in_sizes, int n_in,
                              void* d_out, int out_size) {
    const float* pred    = (const float*)d_in[0];
    const float* full    = (const float*)d_in[1];
    const float* partial = (const float*)d_in[2];
    const float* mu      = (const float*)d_in[3];
    const float* logvar  = (const float*)d_in[4];
    float* out = (float*)d_out;

    float *gm, *pt;
    cudaGetSymbolAddress((void**)&gm, g_min);
    cudaGetSymbolAddress((void**)&pt, g_partial);

    // One memset: 0x7f7f7f7f = 3.39e38 > any real squared distance.
    cudaMemsetAsync(gm, 0x7f, MIN_TOTAL * sizeof(float));

    fused_rowmin_kernel<<<GRID, THREADS>>>(pred, full, partial, gm);

    reduce1_kernel<<<RBLKS, 256>>>(gm, mu, logvar, pt);
    reduce2_kernel<<<1, 128>>>(pt, out);
}